// round 12
// baseline (speedup 1.0000x reference)
#include <cuda_runtime.h>
#include <cuda_fp16.h>
#include <cstdint>

#define NMAX 100000
#define EMAX 1600000
#define HDIM 128
#define FUSE_GRID 592   // 4 blocks/SM x 148 SMs — guaranteed co-resident

// Scratch (static device globals — no runtime allocation, zero-initialized).
__device__                int    g_total;                       // bucket cursor base
__device__                int    g_bar_arrive;                  // sw barrier arrivals
__device__                int    g_bar_release;                 // sw barrier flag
__device__ __align__(128) int    g_cnt [NMAX];                  // incoming-edge count
__device__ __align__(128) int    g_off [NMAX];                  // bucket offsets
__device__ __align__(128) int    g_cur [NMAX];                  // bucket cursors
__device__ __align__(128) float  g_dinv[NMAX];                  // 1/sqrt(deg)
__device__ __align__(128) float2 g_edge[EMAX];                  // {src bits, norm} dst-bucketed
__device__ __align__(256) float  g_h   [(size_t)NMAX * HDIM];   // x @ W_conv (fp32)
__device__ __align__(256) __half g_h16 [(size_t)NMAX * HDIM];   // x @ W_conv (fp16 gather copy)
__device__ __align__(256) float  g_hs  [(size_t)NMAX * HDIM];   // x @ W_skip

// Block-local dtype detect: int64 little-endian indices < 2^32 have zero
// high words across the first 64 entries.
__device__ __forceinline__ int detect_is64(const int* __restrict__ ei32) {
    int ornz = 0;
#pragma unroll
    for (int k = 0; k < 64; k++) ornz |= ei32[2 * k + 1];
    return (ornz == 0) ? 1 : 0;
}

__device__ __forceinline__ void decode_edge(const void* __restrict__ ei, int E,
                                            int n, int e, int is64,
                                            int& src, int& dst) {
    if (is64) {
        src = (int)((const long long*)ei)[e];
        dst = (int)((const long long*)ei)[(size_t)E + e];
    } else {
        src = ((const int*)ei)[e];
        dst = ((const int*)ei)[(size_t)E + e];
    }
    src = min(max(src, 0), n - 1);
    dst = min(max(dst, 0), n - 1);
}

// ---------------------------------------------------------------- degree histogram
__global__ void k_degree(const void* __restrict__ ei, int E, int n) {
    __shared__ int s_is64;
    if (threadIdx.x == 0) s_is64 = detect_is64((const int*)ei);
    __syncthreads();
    int is64 = s_is64;
    int e = blockIdx.x * blockDim.x + threadIdx.x;
    if (e >= E) return;
    int src, dst;
    decode_edge(ei, E, n, e, is64, src, dst);
    atomicAdd(&g_cnt[dst], 1);
}

// ---------------------------------------------------------------- offsets + bucket (fused,
// persistent grid + software global barrier between phases)
__global__ __launch_bounds__(256) void k_offbucket(const void* __restrict__ ei,
                                                   int E, int n) {
    __shared__ int wsum[8];
    __shared__ int bbase;
    __shared__ int s_is64;
    const int tid  = threadIdx.x;
    const int lane = tid & 31;
    const int wid  = tid >> 5;

    // ---- phase A: offsets (scan-free) + dinv, grid-stride over 256-node slices
    int nslices = (n + 255) >> 8;
    for (int s = blockIdx.x; s < nslices; s += gridDim.x) {
        int i = s * 256 + tid;
        int c = (i < n) ? g_cnt[i] : 0;
        int v = c;
#pragma unroll
        for (int o = 1; o < 32; o <<= 1) {
            int t = __shfl_up_sync(0xffffffffu, v, o);
            if (lane >= o) v += t;
        }
        if (lane == 31) wsum[wid] = v;
        __syncthreads();
        if (tid == 0) {
            int run = 0;
#pragma unroll
            for (int w = 0; w < 8; w++) { int t = wsum[w]; wsum[w] = run; run += t; }
            bbase = atomicAdd(&g_total, run);
        }
        __syncthreads();
        if (i < n) {
            int excl = bbase + wsum[wid] + v - c;
            g_off[i] = excl;
            g_cur[i] = excl;
            g_dinv[i] = rsqrtf((float)c + 2.0f);   // improved=True: +2 self-loop
        }
        __syncthreads();   // wsum/bbase reuse
    }

    // ---- software global barrier (all FUSE_GRID blocks co-resident)
    __threadfence();
    if (tid == 0) {
        int pos = atomicAdd(&g_bar_arrive, 1);
        if (pos == gridDim.x - 1) atomicExch(&g_bar_release, 1);
        while (atomicAdd(&g_bar_release, 0) == 0) {}
    }
    __syncthreads();

    if (tid == 0) s_is64 = detect_is64((const int*)ei);
    __syncthreads();
    int is64 = s_is64;

    // ---- phase B: bucket (counting sort by dst), grid-stride over edges
    for (int e = blockIdx.x * 256 + tid; e < E; e += gridDim.x * 256) {
        int src, dst;
        decode_edge(ei, E, n, e, is64, src, dst);
        float nrm = g_dinv[src] * g_dinv[dst];
        int pos = atomicAdd(&g_cur[dst], 1);
        g_edge[pos] = make_float2(__int_as_float(src), nrm);
    }
}

// ---------------------------------------------------------------- HMMA dual GEMM
// mma.sync m16n8k16 fp16 (base ISA). Split precision:
//   D = x_hi·W_hi + x_lo·W_hi + x_hi·W_lo   (lo·lo term ~2^-22, dropped)
#define SA_STR 40
#define SB_STR 40
#define SA_HALVES (128 * SA_STR)            // per hi/lo tile
#define SB_HALVES (256 * SB_STR)
#define SMEM_MMA ((2 * SA_HALVES + 2 * SB_HALVES) * 2)   // 61440 bytes

__device__ __forceinline__ void mma16816(float* d, const uint32_t* a,
                                         uint32_t b0, uint32_t b1) {
    asm volatile(
        "mma.sync.aligned.m16n8k16.row.col.f32.f16.f16.f32 "
        "{%0,%1,%2,%3}, {%4,%5,%6,%7}, {%8,%9}, {%0,%1,%2,%3};"
        : "+f"(d[0]), "+f"(d[1]), "+f"(d[2]), "+f"(d[3])
        : "r"(a[0]), "r"(a[1]), "r"(a[2]), "r"(a[3]), "r"(b0), "r"(b1));
}

__device__ __forceinline__ uint32_t pack_half2(float a, float b) {
    __half2 h = __floats2half2_rn(a, b);
    return *(uint32_t*)&h;
}

__global__ __launch_bounds__(512) void k_gemm_mma(const float* __restrict__ x,
                                                  const float* __restrict__ Wc,
                                                  const float* __restrict__ Ws,
                                                  int n) {
    extern __shared__ __align__(16) __half smem[];
    __half* sAhi = smem;
    __half* sAlo = sAhi + SA_HALVES;
    __half* sBhi = sAlo + SA_HALVES;
    __half* sBlo = sBhi + SB_HALVES;

    const int tid  = threadIdx.x;
    const int wid  = tid >> 5;
    const int lane = tid & 31;
    const int g    = lane >> 2;     // group id (0..7)
    const int tg   = lane & 3;      // thread in group
    const int mw   = (wid & 3) * 32;    // warp M offset (rows)
    const int nw   = (wid >> 2) * 64;   // warp N offset (cols of 256)
    const int node0 = blockIdx.x * 128;

    float d[2][8][4];
#pragma unroll
    for (int mi = 0; mi < 2; mi++)
#pragma unroll
        for (int ni = 0; ni < 8; ni++)
#pragma unroll
            for (int q = 0; q < 4; q++) d[mi][ni][q] = 0.f;

    for (int kc = 0; kc < 4; kc++) {
        // ---- load + split x chunk: 128 rows x 32 k (1024 float4, 2/thread)
#pragma unroll
        for (int i = 0; i < 2; i++) {
            int f4  = i * 512 + tid;
            int row = f4 >> 3;
            int k4  = f4 & 7;
            int node = node0 + row;
            float4 v = make_float4(0.f, 0.f, 0.f, 0.f);
            if (node < n) v = ((const float4*)x)[(size_t)node * 32 + kc * 8 + k4];
            float hx = __half2float(__float2half_rn(v.x));
            float hy = __half2float(__float2half_rn(v.y));
            float hz = __half2float(__float2half_rn(v.z));
            float hw = __half2float(__float2half_rn(v.w));
            int base = row * SA_STR + k4 * 4;
            *(uint32_t*)&sAhi[base]     = pack_half2(hx, hy);
            *(uint32_t*)&sAhi[base + 2] = pack_half2(hz, hw);
            *(uint32_t*)&sAlo[base]     = pack_half2(v.x - hx, v.y - hy);
            *(uint32_t*)&sAlo[base + 2] = pack_half2(v.z - hz, v.w - hw);
        }
        // ---- load + split W chunk: 32 k x 256 cols (8192 elems, 16/thread)
#pragma unroll
        for (int i = 0; i < 16; i++) {
            int f    = i * 512 + tid;
            int k    = f >> 8;
            int ncol = f & 255;
            int krow = kc * 32 + k;
            float v = (ncol < 128) ? Wc[krow * 128 + ncol]
                                   : Ws[krow * 128 + (ncol - 128)];
            __half hi = __float2half_rn(v);
            sBhi[ncol * SB_STR + k] = hi;
            sBlo[ncol * SB_STR + k] = __float2half_rn(v - __half2float(hi));
        }
        __syncthreads();

        // ---- 3 split passes x 2 k16 steps
#pragma unroll
        for (int p = 0; p < 3; p++) {
            const __half* A = (p == 1) ? sAlo : sAhi;
            const __half* B = (p == 2) ? sBlo : sBhi;
#pragma unroll
            for (int kk = 0; kk < 32; kk += 16) {
                uint32_t a[2][4];
#pragma unroll
                for (int mi = 0; mi < 2; mi++) {
                    int r0 = (mw + mi * 16 + g) * SA_STR + kk + tg * 2;
                    int r1 = r0 + 8 * SA_STR;
                    a[mi][0] = *(const uint32_t*)(A + r0);
                    a[mi][1] = *(const uint32_t*)(A + r1);
                    a[mi][2] = *(const uint32_t*)(A + r0 + 8);
                    a[mi][3] = *(const uint32_t*)(A + r1 + 8);
                }
#pragma unroll
                for (int ni = 0; ni < 8; ni++) {
                    int nb = (nw + ni * 8 + g) * SB_STR + kk + tg * 2;
                    uint32_t b0 = *(const uint32_t*)(B + nb);
                    uint32_t b1 = *(const uint32_t*)(B + nb + 8);
                    mma16816(d[0][ni], a[0], b0, b1);
                    mma16816(d[1][ni], a[1], b0, b1);
                }
            }
        }
        __syncthreads();
    }

    // ---- epilogue
#pragma unroll
    for (int mi = 0; mi < 2; mi++) {
#pragma unroll
        for (int hr = 0; hr < 2; hr++) {
            int node = node0 + mw + mi * 16 + g + hr * 8;
            if (node >= n) continue;
#pragma unroll
            for (int ni = 0; ni < 8; ni++) {
                int col = nw + ni * 8 + tg * 2;
                float v0 = d[mi][ni][hr * 2 + 0];
                float v1 = d[mi][ni][hr * 2 + 1];
                if (col < 128) {
                    *(float2*)&g_h[(size_t)node * HDIM + col] = make_float2(v0, v1);
                    *(uint32_t*)&g_h16[(size_t)node * HDIM + col] = pack_half2(v0, v1);
                } else {
                    *(float2*)&g_hs[(size_t)node * HDIM + (col - 128)] =
                        make_float2(v0, v1);
                }
            }
        }
    }
}

// ---------------------------------------------------------------- fused aggregation + epilogue
// One warp per node, lane l owns features [4l, 4l+4). fp16 gathers (256 B/edge),
// broadcast metadata, unroll-8. Also resets g_cnt/g_total/barrier for next call.
__global__ __launch_bounds__(256) void k_agg(const float* __restrict__ bconv,
                                             const float* __restrict__ bskip,
                                             float* __restrict__ out, int n) {
    if (blockIdx.x == 0 && threadIdx.x == 0) {
        g_total = 0;
        g_bar_arrive = 0;
        g_bar_release = 0;
    }
    int node = (blockIdx.x * blockDim.x + threadIdx.x) >> 5;
    int lane = threadIdx.x & 31;
    if (node >= n) return;

    const int beg = g_off[node];
    const int cnt = g_cnt[node];
    const int end = beg + cnt;
    if (lane == 0) g_cnt[node] = 0;    // reset for next call

    float4 acc = make_float4(0.f, 0.f, 0.f, 0.f);
    int j = beg;
    for (; j + 8 <= end; j += 8) {
        float2 e[8];
        uint2  h[8];
#pragma unroll
        for (int u = 0; u < 8; u++) e[u] = g_edge[j + u];
#pragma unroll
        for (int u = 0; u < 8; u++)
            h[u] = ((const uint2*)&g_h16[(size_t)__float_as_int(e[u].x) * HDIM])[lane];
#pragma unroll
        for (int u = 0; u < 8; u++) {
            float2 f01 = __half22float2(*(__half2*)&h[u].x);
            float2 f23 = __half22float2(*(__half2*)&h[u].y);
            acc.x += e[u].y * f01.x;
            acc.y += e[u].y * f01.y;
            acc.z += e[u].y * f23.x;
            acc.w += e[u].y * f23.y;
        }
    }
    for (; j < end; j++) {
        float2 e  = g_edge[j];
        uint2  hv = ((const uint2*)&g_h16[(size_t)__float_as_int(e.x) * HDIM])[lane];
        float2 f01 = __half22float2(*(__half2*)&hv.x);
        float2 f23 = __half22float2(*(__half2*)&hv.y);
        acc.x += e.y * f01.x;
        acc.y += e.y * f01.y;
        acc.z += e.y * f23.x;
        acc.w += e.y * f23.y;
    }

    float di = g_dinv[node];
    float sw = 2.0f * di * di;

    float4 h4  = ((const float4*)&g_h [(size_t)node * HDIM])[lane];
    float4 hs4 = ((const float4*)&g_hs[(size_t)node * HDIM])[lane];
    float4 bc  = ((const float4*)bconv)[lane];
    float4 bs  = ((const float4*)bskip)[lane];

    float4 o;
    o.x = acc.x + sw * h4.x + bc.x + hs4.x + bs.x;
    o.y = acc.y + sw * h4.y + bc.y + hs4.y + bs.y;
    o.z = acc.z + sw * h4.z + bc.z + hs4.z + bs.z;
    o.w = acc.w + sw * h4.w + bc.w + hs4.w + bs.w;

    o.x = (o.x > 0.f) ? o.x : 0.1f * (__expf(o.x) - 1.0f);
    o.y = (o.y > 0.f) ? o.y : 0.1f * (__expf(o.y) - 1.0f);
    o.z = (o.z > 0.f) ? o.z : 0.1f * (__expf(o.z) - 1.0f);
    o.w = (o.w > 0.f) ? o.w : 0.1f * (__expf(o.w) - 1.0f);

    ((float4*)&out[(size_t)node * HDIM])[lane] = o;
}

// ---------------------------------------------------------------- launch
// 4 launches total: gemm (s2), degree, offbucket, agg.
extern "C" void kernel_launch(void* const* d_in, const int* in_sizes, int n_in,
                              void* d_out, int out_size) {
    const float* x  = (const float*)d_in[0];
    const void*  ei = d_in[1];
    const float* Wc = (const float*)d_in[2];
    const float* bc = (const float*)d_in[3];
    const float* Ws = (const float*)d_in[4];
    const float* bs = (const float*)d_in[5];
    float* out = (float*)d_out;

    const int n = in_sizes[0] / HDIM;
    const int E = in_sizes[1] / 2;

    static cudaStream_t s2 = []() {
        cudaStream_t s; cudaStreamCreateWithFlags(&s, cudaStreamNonBlocking); return s;
    }();
    static cudaEvent_t ev_fork = []() {
        cudaEvent_t e; cudaEventCreateWithFlags(&e, cudaEventDisableTiming); return e;
    }();
    static cudaEvent_t ev_gemm = []() {
        cudaEvent_t e; cudaEventCreateWithFlags(&e, cudaEventDisableTiming); return e;
    }();
    static bool attr_done = []() {
        cudaFuncSetAttribute(k_gemm_mma,
                             cudaFuncAttributeMaxDynamicSharedMemorySize, SMEM_MMA);
        return true;
    }();
    (void)attr_done;

    // Fork: GEMM on s2, concurrent with edge preprocessing on the main stream.
    cudaEventRecord(ev_fork, 0);
    cudaStreamWaitEvent(s2, ev_fork, 0);
    k_gemm_mma<<<(n + 127) / 128, 512, SMEM_MMA, s2>>>(x, Wc, Ws, n);
    cudaEventRecord(ev_gemm, s2);

    k_degree   <<<(E + 255) / 256, 256>>>(ei, E, n);
    k_offbucket<<<FUSE_GRID, 256>>>(ei, E, n);

    // Join: aggregation needs both the bucketed edges and g_h/g_hs.
    cudaStreamWaitEvent(0, ev_gemm, 0);
    long long athreads = (long long)n * 32;
    k_agg<<<(unsigned)((athreads + 255) / 256), 256>>>(bc, bs, out, n);
}

// round 13
// speedup vs baseline: 1.6561x; 1.6561x over previous
#include <cuda_runtime.h>
#include <cuda_fp16.h>
#include <cstdint>

#define NMAX 100000
#define EMAX 1600000
#define HDIM 128

// Scratch (static device globals — no runtime allocation).
__device__ __align__(16)  int    g_is64;                        // edge dtype flag
__device__                int    g_total;                       // bucket cursor base
__device__ __align__(128) int    g_cnt [NMAX];                  // incoming-edge count
__device__ __align__(128) int    g_off [NMAX];                  // bucket offsets
__device__ __align__(128) int    g_cur [NMAX];                  // bucket cursors
__device__ __align__(128) float  g_dinv[NMAX];                  // 1/sqrt(deg)
__device__ __align__(128) float2 g_edge[EMAX];                  // {src bits, norm} dst-bucketed
__device__ __align__(256) __half g_h16 [(size_t)NMAX * HDIM];   // x @ W_conv (fp16)
__device__ __align__(256) float  g_hs  [(size_t)NMAX * HDIM];   // x @ W_skip (fp32)

__device__ __forceinline__ void decode_edge(const void* __restrict__ ei, int E,
                                            int n, int e, int& src, int& dst) {
    if (g_is64) {
        src = (int)((const long long*)ei)[e];
        dst = (int)((const long long*)ei)[(size_t)E + e];
    } else {
        src = ((const int*)ei)[e];
        dst = ((const int*)ei)[(size_t)E + e];
    }
    src = min(max(src, 0), n - 1);
    dst = min(max(dst, 0), n - 1);
}

// ---------------------------------------------------------------- init (+ dtype detect)
__global__ void k_init(const int* __restrict__ ei32, int n) {
    int i = blockIdx.x * blockDim.x + threadIdx.x;
    if (i == 0) {
        int ornz = 0;
        for (int k = 0; k < 64; k++) ornz |= ei32[2 * k + 1];
        g_is64 = (ornz == 0) ? 1 : 0;
        g_total = 0;
    }
    if (i < n) g_cnt[i] = 0;
}

// ---------------------------------------------------------------- degree histogram
__global__ void k_degree(const void* __restrict__ ei, int E, int n) {
    int e = blockIdx.x * blockDim.x + threadIdx.x;
    if (e >= E) return;
    int src, dst;
    decode_edge(ei, E, n, e, src, dst);
    atomicAdd(&g_cnt[dst], 1);
}

// ---------------------------------------------------------------- offsets (scan-free) + dinv
__global__ void k_offsets(int n) {
    __shared__ int wsum[8];
    __shared__ int bbase;
    int i    = blockIdx.x * 256 + threadIdx.x;
    int lane = threadIdx.x & 31;
    int wid  = threadIdx.x >> 5;

    int c = (i < n) ? g_cnt[i] : 0;
    int v = c;
#pragma unroll
    for (int o = 1; o < 32; o <<= 1) {
        int t = __shfl_up_sync(0xffffffffu, v, o);
        if (lane >= o) v += t;
    }
    if (lane == 31) wsum[wid] = v;
    __syncthreads();
    if (threadIdx.x == 0) {
        int run = 0;
#pragma unroll
        for (int w = 0; w < 8; w++) { int t = wsum[w]; wsum[w] = run; run += t; }
        bbase = atomicAdd(&g_total, run);
    }
    __syncthreads();
    if (i < n) {
        int excl = bbase + wsum[wid] + v - c;
        g_off[i] = excl;
        g_cur[i] = excl;
        g_dinv[i] = rsqrtf((float)c + 2.0f);   // improved=True: +2 self-loop
    }
}

// ---------------------------------------------------------------- bucket (counting sort by dst)
__global__ void k_bucket(const void* __restrict__ ei, int E, int n) {
    int e = blockIdx.x * blockDim.x + threadIdx.x;
    if (e >= E) return;
    int src, dst;
    decode_edge(ei, E, n, e, src, dst);
    float nrm = g_dinv[src] * g_dinv[dst];
    int pos = atomicAdd(&g_cur[dst], 1);
    g_edge[pos] = make_float2(__int_as_float(src), nrm);
}

// ---------------------------------------------------------------- HMMA dual GEMM
// mma.sync m16n8k16 fp16 (base ISA). Split precision:
//   D = x_hi·W_hi + x_lo·W_hi + x_hi·W_lo   (lo·lo term ~2^-22, dropped)
#define SA_STR 40
#define SB_STR 40
#define SA_HALVES (128 * SA_STR)            // per hi/lo tile
#define SB_HALVES (256 * SB_STR)
#define SMEM_MMA ((2 * SA_HALVES + 2 * SB_HALVES) * 2)   // 61440 bytes

__device__ __forceinline__ void mma16816(float* d, const uint32_t* a,
                                         uint32_t b0, uint32_t b1) {
    asm volatile(
        "mma.sync.aligned.m16n8k16.row.col.f32.f16.f16.f32 "
        "{%0,%1,%2,%3}, {%4,%5,%6,%7}, {%8,%9}, {%0,%1,%2,%3};"
        : "+f"(d[0]), "+f"(d[1]), "+f"(d[2]), "+f"(d[3])
        : "r"(a[0]), "r"(a[1]), "r"(a[2]), "r"(a[3]), "r"(b0), "r"(b1));
}

__device__ __forceinline__ uint32_t pack_half2(float a, float b) {
    __half2 h = __floats2half2_rn(a, b);
    return *(uint32_t*)&h;
}

__global__ __launch_bounds__(512) void k_gemm_mma(const float* __restrict__ x,
                                                  const float* __restrict__ Wc,
                                                  const float* __restrict__ Ws,
                                                  int n) {
    extern __shared__ __align__(16) __half smem[];
    __half* sAhi = smem;
    __half* sAlo = sAhi + SA_HALVES;
    __half* sBhi = sAlo + SA_HALVES;
    __half* sBlo = sBhi + SB_HALVES;

    const int tid  = threadIdx.x;
    const int wid  = tid >> 5;
    const int lane = tid & 31;
    const int g    = lane >> 2;     // group id (0..7)
    const int tg   = lane & 3;      // thread in group
    const int mw   = (wid & 3) * 32;    // warp M offset (rows)
    const int nw   = (wid >> 2) * 64;   // warp N offset (cols of 256)
    const int node0 = blockIdx.x * 128;

    float d[2][8][4];
#pragma unroll
    for (int mi = 0; mi < 2; mi++)
#pragma unroll
        for (int ni = 0; ni < 8; ni++)
#pragma unroll
            for (int q = 0; q < 4; q++) d[mi][ni][q] = 0.f;

    for (int kc = 0; kc < 4; kc++) {
        // ---- load + split x chunk: 128 rows x 32 k (1024 float4, 2/thread)
#pragma unroll
        for (int i = 0; i < 2; i++) {
            int f4  = i * 512 + tid;
            int row = f4 >> 3;
            int k4  = f4 & 7;
            int node = node0 + row;
            float4 v = make_float4(0.f, 0.f, 0.f, 0.f);
            if (node < n) v = ((const float4*)x)[(size_t)node * 32 + kc * 8 + k4];
            float hx = __half2float(__float2half_rn(v.x));
            float hy = __half2float(__float2half_rn(v.y));
            float hz = __half2float(__float2half_rn(v.z));
            float hw = __half2float(__float2half_rn(v.w));
            int base = row * SA_STR + k4 * 4;
            *(uint32_t*)&sAhi[base]     = pack_half2(hx, hy);
            *(uint32_t*)&sAhi[base + 2] = pack_half2(hz, hw);
            *(uint32_t*)&sAlo[base]     = pack_half2(v.x - hx, v.y - hy);
            *(uint32_t*)&sAlo[base + 2] = pack_half2(v.z - hz, v.w - hw);
        }
        // ---- load + split W chunk: 32 k x 256 cols (8192 elems, 16/thread)
#pragma unroll
        for (int i = 0; i < 16; i++) {
            int f    = i * 512 + tid;
            int k    = f >> 8;
            int ncol = f & 255;
            int krow = kc * 32 + k;
            float v = (ncol < 128) ? Wc[krow * 128 + ncol]
                                   : Ws[krow * 128 + (ncol - 128)];
            __half hi = __float2half_rn(v);
            sBhi[ncol * SB_STR + k] = hi;
            sBlo[ncol * SB_STR + k] = __float2half_rn(v - __half2float(hi));
        }
        __syncthreads();

        // ---- 3 split passes x 2 k16 steps
#pragma unroll
        for (int p = 0; p < 3; p++) {
            const __half* A = (p == 1) ? sAlo : sAhi;
            const __half* B = (p == 2) ? sBlo : sBhi;
#pragma unroll
            for (int kk = 0; kk < 32; kk += 16) {
                uint32_t a[2][4];
#pragma unroll
                for (int mi = 0; mi < 2; mi++) {
                    int r0 = (mw + mi * 16 + g) * SA_STR + kk + tg * 2;
                    int r1 = r0 + 8 * SA_STR;
                    a[mi][0] = *(const uint32_t*)(A + r0);
                    a[mi][1] = *(const uint32_t*)(A + r1);
                    a[mi][2] = *(const uint32_t*)(A + r0 + 8);
                    a[mi][3] = *(const uint32_t*)(A + r1 + 8);
                }
#pragma unroll
                for (int ni = 0; ni < 8; ni++) {
                    int nb = (nw + ni * 8 + g) * SB_STR + kk + tg * 2;
                    uint32_t b0 = *(const uint32_t*)(B + nb);
                    uint32_t b1 = *(const uint32_t*)(B + nb + 8);
                    mma16816(d[0][ni], a[0], b0, b1);
                    mma16816(d[1][ni], a[1], b0, b1);
                }
            }
        }
        __syncthreads();
    }

    // ---- epilogue: conv half -> fp16 only; skip half -> fp32
#pragma unroll
    for (int mi = 0; mi < 2; mi++) {
#pragma unroll
        for (int hr = 0; hr < 2; hr++) {
            int node = node0 + mw + mi * 16 + g + hr * 8;
            if (node >= n) continue;
#pragma unroll
            for (int ni = 0; ni < 8; ni++) {
                int col = nw + ni * 8 + tg * 2;
                float v0 = d[mi][ni][hr * 2 + 0];
                float v1 = d[mi][ni][hr * 2 + 1];
                if (col < 128) {
                    *(uint32_t*)&g_h16[(size_t)node * HDIM + col] = pack_half2(v0, v1);
                } else {
                    *(float2*)&g_hs[(size_t)node * HDIM + (col - 128)] =
                        make_float2(v0, v1);
                }
            }
        }
    }
}

// ---------------------------------------------------------------- fused aggregation + epilogue
// TWO warps per node (independent latency chains): warp pair splits the edge
// list, partials combined via smem; even warp does the epilogue.
// Lane l owns features [4l, 4l+4); fp16 gathers, broadcast meta, unroll-8.
__global__ __launch_bounds__(256) void k_agg(const float* __restrict__ bconv,
                                             const float* __restrict__ bskip,
                                             float* __restrict__ out, int n) {
    __shared__ float4 s_part[4][32];
    const int tid  = threadIdx.x;
    const int lane = tid & 31;
    const int wid  = tid >> 5;
    const int nloc = wid >> 1;          // node slot in block (0..3)
    const int sw   = wid & 1;           // sub-warp of the pair
    const int node = blockIdx.x * 4 + nloc;
    const bool valid = (node < n);

    int beg = 0, cnt = 0;
    if (valid) { beg = g_off[node]; cnt = g_cnt[node]; }
    const int half = cnt >> 1;
    const int jb = sw ? (beg + half) : beg;
    const int je = sw ? (beg + cnt)  : (beg + half);

    float4 acc = make_float4(0.f, 0.f, 0.f, 0.f);
    int j = jb;
    for (; j + 8 <= je; j += 8) {
        float2 e[8];
        uint2  h[8];
#pragma unroll
        for (int u = 0; u < 8; u++) e[u] = g_edge[j + u];
#pragma unroll
        for (int u = 0; u < 8; u++)
            h[u] = ((const uint2*)&g_h16[(size_t)__float_as_int(e[u].x) * HDIM])[lane];
#pragma unroll
        for (int u = 0; u < 8; u++) {
            float2 f01 = __half22float2(*(__half2*)&h[u].x);
            float2 f23 = __half22float2(*(__half2*)&h[u].y);
            acc.x += e[u].y * f01.x;
            acc.y += e[u].y * f01.y;
            acc.z += e[u].y * f23.x;
            acc.w += e[u].y * f23.y;
        }
    }
    for (; j < je; j++) {
        float2 e  = g_edge[j];
        uint2  hv = ((const uint2*)&g_h16[(size_t)__float_as_int(e.x) * HDIM])[lane];
        float2 f01 = __half22float2(*(__half2*)&hv.x);
        float2 f23 = __half22float2(*(__half2*)&hv.y);
        acc.x += e.y * f01.x;
        acc.y += e.y * f01.y;
        acc.z += e.y * f23.x;
        acc.w += e.y * f23.y;
    }

    if (sw == 1) s_part[nloc][lane] = acc;
    __syncthreads();

    if (sw == 0 && valid) {
        float4 p = s_part[nloc][lane];
        acc.x += p.x; acc.y += p.y; acc.z += p.z; acc.w += p.w;

        float di = g_dinv[node];
        float swt = 2.0f * di * di;

        uint2  hh  = ((const uint2*)&g_h16[(size_t)node * HDIM])[lane];
        float2 h01 = __half22float2(*(__half2*)&hh.x);
        float2 h23 = __half22float2(*(__half2*)&hh.y);
        float4 hs4 = ((const float4*)&g_hs[(size_t)node * HDIM])[lane];
        float4 bc  = ((const float4*)bconv)[lane];
        float4 bs  = ((const float4*)bskip)[lane];

        float4 o;
        o.x = acc.x + swt * h01.x + bc.x + hs4.x + bs.x;
        o.y = acc.y + swt * h01.y + bc.y + hs4.y + bs.y;
        o.z = acc.z + swt * h23.x + bc.z + hs4.z + bs.z;
        o.w = acc.w + swt * h23.y + bc.w + hs4.w + bs.w;

        o.x = (o.x > 0.f) ? o.x : 0.1f * (__expf(o.x) - 1.0f);
        o.y = (o.y > 0.f) ? o.y : 0.1f * (__expf(o.y) - 1.0f);
        o.z = (o.z > 0.f) ? o.z : 0.1f * (__expf(o.z) - 1.0f);
        o.w = (o.w > 0.f) ? o.w : 0.1f * (__expf(o.w) - 1.0f);

        ((float4*)&out[(size_t)node * HDIM])[lane] = o;
    }
}

// ---------------------------------------------------------------- launch
extern "C" void kernel_launch(void* const* d_in, const int* in_sizes, int n_in,
                              void* d_out, int out_size) {
    const float* x  = (const float*)d_in[0];
    const void*  ei = d_in[1];
    const float* Wc = (const float*)d_in[2];
    const float* bc = (const float*)d_in[3];
    const float* Ws = (const float*)d_in[4];
    const float* bs = (const float*)d_in[5];
    float* out = (float*)d_out;

    const int n = in_sizes[0] / HDIM;
    const int E = in_sizes[1] / 2;

    static cudaStream_t s2 = []() {
        cudaStream_t s; cudaStreamCreateWithFlags(&s, cudaStreamNonBlocking); return s;
    }();
    static cudaEvent_t ev_fork = []() {
        cudaEvent_t e; cudaEventCreateWithFlags(&e, cudaEventDisableTiming); return e;
    }();
    static cudaEvent_t ev_gemm = []() {
        cudaEvent_t e; cudaEventCreateWithFlags(&e, cudaEventDisableTiming); return e;
    }();
    static bool attr_done = []() {
        cudaFuncSetAttribute(k_gemm_mma,
                             cudaFuncAttributeMaxDynamicSharedMemorySize, SMEM_MMA);
        return true;
    }();
    (void)attr_done;

    // Fork: GEMM on s2, concurrent with edge preprocessing on the main stream.
    cudaEventRecord(ev_fork, 0);
    cudaStreamWaitEvent(s2, ev_fork, 0);
    k_gemm_mma<<<(n + 127) / 128, 512, SMEM_MMA, s2>>>(x, Wc, Ws, n);
    cudaEventRecord(ev_gemm, s2);

    k_init   <<<(n + 255) / 256, 256>>>((const int*)ei, n);
    k_degree <<<(E + 255) / 256, 256>>>(ei, E, n);
    k_offsets<<<(n + 255) / 256, 256>>>(n);
    k_bucket <<<(E + 255) / 256, 256>>>(ei, E, n);

    // Join: aggregation needs both the bucketed edges and g_h16/g_hs.
    cudaStreamWaitEvent(0, ev_gemm, 0);
    k_agg<<<(n + 3) / 4, 256>>>(bc, bs, out, n);
}